// round 1
// baseline (speedup 1.0000x reference)
#include <cuda_runtime.h>
#include <cuda_bf16.h>

#define N_NODES 20000
#define N_EDGES 320000
#define NF 128
#define NH 64
#define NG 16
#define NL 5
#define EPS 1e-5f

#define NBLK_NODES ((N_NODES + 127) / 128)   // 157

// ---------------- scratch (device globals; float4 for 16B alignment) -------
__device__ float4 g_h4[N_NODES * NF / 4];     // running node features h
__device__ float4 g_m4[N_NODES * NF / 4];     // per-node MLP output m
__device__ float4 g_g4[N_NODES * NF / 4];     // aggregation / norm buffer g
__device__ float4 g_gsum4[NG * NF / 4];       // per-graph feature sums
__device__ float4 g_vsum4[NG * NF / 4];       // per-graph variance sums
__device__ float4 g_psum4[NG * NF / 4];       // pooled sums
__device__ float  g_cnt[NG];                  // per-graph node counts (>=1)
__device__ int    g_src[N_EDGES];
__device__ int    g_dst[N_EDGES];
__device__ int    g_batch[N_NODES];

// ---------------- index width detect + convert -----------------------------
// edge_index / batch are int64 in the reference, but JAX default config
// downgrades to int32. Detect: if int64 (little-endian), the high 32-bit word
// of each element is 0; for int32 data the odd words are random node ids.
__global__ void convert_kernel(const int* __restrict__ ei_raw,
                               const int* __restrict__ batch_raw) {
    __shared__ int s_is64;
    if (threadIdx.x == 0) {
        int all0 = 1;
        #pragma unroll 1
        for (int i = 1; i < 256; i += 2) all0 &= (ei_raw[i] == 0);
        s_is64 = all0;
    }
    __syncthreads();
    int is64 = s_is64;
    int idx = blockIdx.x * blockDim.x + threadIdx.x;
    const int total = 2 * N_EDGES + N_NODES;
    if (idx >= total) return;
    if (idx < N_EDGES) {
        g_src[idx] = is64 ? ei_raw[2 * idx] : ei_raw[idx];
    } else if (idx < 2 * N_EDGES) {
        int e = idx - N_EDGES;
        g_dst[e] = is64 ? ei_raw[2 * N_EDGES + 2 * e] : ei_raw[N_EDGES + e];
    } else {
        int n = idx - 2 * N_EDGES;
        g_batch[n] = is64 ? batch_raw[2 * n] : batch_raw[n];
    }
}

// ---------------- per-graph counts + zero pooled sums ----------------------
__global__ void cnt_kernel() {
    __shared__ float hist[NG];
    int tid = threadIdx.x;
    if (tid < NG) hist[tid] = 0.f;
    __syncthreads();
    for (int n = tid; n < N_NODES; n += blockDim.x)
        atomicAdd(&hist[g_batch[n]], 1.f);
    __syncthreads();
    if (tid < NG) g_cnt[tid] = fmaxf(hist[tid], 1.f);
    float* ps = (float*)g_psum4;
    for (int i = tid; i < NG * NF; i += blockDim.x) ps[i] = 0.f;
}

// ---------------- fused per-node MLP:  m = relu(h@W1+b1)@W2+b2 -------------
// One thread per node. W1/W2/bias + a transposed h tile live in smem.
// Also writes g = m (self-loop term) and block 0 zeros the norm accumulators.
#define SH_STRIDE 129
#define SMEM_MLP_FLOATS (NF * SH_STRIDE + NF * NH + NH * NF + NH + NF)
#define SMEM_MLP_BYTES (SMEM_MLP_FLOATS * 4)

__global__ void mlp_kernel(const float* __restrict__ x, int first,
                           const float* __restrict__ W1, const float* __restrict__ b1,
                           const float* __restrict__ W2, const float* __restrict__ b2) {
    extern __shared__ float sm[];
    float* sh  = sm;                       // [128][129] transposed h tile
    float* sW1 = sm + NF * SH_STRIDE;      // [128][64]
    float* sW2 = sW1 + NF * NH;            // [64][128]
    float* sb1 = sW2 + NH * NF;            // [64]
    float* sb2 = sb1 + NH;                 // [128]

    int tid = threadIdx.x;
    const float* hin = first ? x : (const float*)g_h4;

    for (int i = tid; i < NF * NH; i += 128) { sW1[i] = W1[i]; sW2[i] = W2[i]; }
    if (tid < NH) sb1[tid] = b1[tid];
    sb2[tid] = b2[tid];

    if (blockIdx.x == 0) {  // zero norm accumulators (consumed 2+ kernels later)
        float* gs = (float*)g_gsum4;
        float* vs = (float*)g_vsum4;
        for (int i = tid; i < NG * NF; i += 128) { gs[i] = 0.f; vs[i] = 0.f; }
    }

    int n0 = blockIdx.x * 128;
    // cooperative coalesced load of h tile, transposed into smem
    for (int idx = tid; idx < 128 * NF; idx += 128) {
        int k = idx & (NF - 1);
        int nl = idx >> 7;
        int n = n0 + nl;
        sh[k * SH_STRIDE + nl] = (n < N_NODES) ? hin[n * NF + k] : 0.f;
    }
    __syncthreads();

    int n = n0 + tid;
    float hid[NH];
    #pragma unroll
    for (int j = 0; j < NH; j++) hid[j] = sb1[j];

    #pragma unroll 8
    for (int k = 0; k < NF; k++) {
        float hk = sh[k * SH_STRIDE + tid];
        const float4* wr = (const float4*)(sW1 + k * NH);
        #pragma unroll
        for (int j4 = 0; j4 < NH / 4; j4++) {
            float4 w = wr[j4];
            hid[4 * j4 + 0] = fmaf(hk, w.x, hid[4 * j4 + 0]);
            hid[4 * j4 + 1] = fmaf(hk, w.y, hid[4 * j4 + 1]);
            hid[4 * j4 + 2] = fmaf(hk, w.z, hid[4 * j4 + 2]);
            hid[4 * j4 + 3] = fmaf(hk, w.w, hid[4 * j4 + 3]);
        }
    }
    #pragma unroll
    for (int j = 0; j < NH; j++) hid[j] = fmaxf(hid[j], 0.f);

    if (n < N_NODES) {
        float4* mo = g_m4 + n * (NF / 4);
        float4* go = g_g4 + n * (NF / 4);
        const float4* w2v = (const float4*)sW2;
        const float4* b2v = (const float4*)sb2;
        #pragma unroll 2
        for (int c4 = 0; c4 < NF / 4; c4++) {
            float4 acc = b2v[c4];
            #pragma unroll
            for (int j = 0; j < NH; j++) {
                float4 w = w2v[j * (NF / 4) + c4];
                acc.x = fmaf(hid[j], w.x, acc.x);
                acc.y = fmaf(hid[j], w.y, acc.y);
                acc.z = fmaf(hid[j], w.z, acc.z);
                acc.w = fmaf(hid[j], w.w, acc.w);
            }
            mo[c4] = acc;
            go[c4] = acc;
        }
    }
}

// ---------------- edge scatter-add:  g[dst] += m[src]  ---------------------
__device__ __forceinline__ void red_add_v4(float* p, float4 v) {
    asm volatile("red.global.add.v4.f32 [%0], {%1, %2, %3, %4};"
                 :: "l"(p), "f"(v.x), "f"(v.y), "f"(v.z), "f"(v.w) : "memory");
}

__global__ void scatter_kernel() {
    int warp = (blockIdx.x * blockDim.x + threadIdx.x) >> 5;
    int lane = threadIdx.x & 31;
    if (warp >= N_EDGES) return;
    int src = g_src[warp];
    int dst = g_dst[warp];
    float4 v = g_m4[src * (NF / 4) + lane];
    red_add_v4((float*)(g_g4 + dst * (NF / 4) + lane), v);
}

// ---------------- segmented sums over sorted batch -------------------------
// mode 0: g -> gsum     mode 1: h -> psum (final pooling)
__global__ void seg_sum_kernel(int mode) {
    int c = threadIdx.x;  // 128 threads = feature
    int n0 = blockIdx.x * 128;
    int nend = min(n0 + 128, N_NODES);
    const float* src = mode ? (const float*)g_h4 : (const float*)g_g4;
    float* dstsum = mode ? (float*)g_psum4 : (float*)g_gsum4;
    int cur = g_batch[n0];
    float acc = 0.f;
    for (int n = n0; n < nend; n++) {
        int b = g_batch[n];
        if (b != cur) {
            atomicAdd(&dstsum[cur * NF + c], acc);
            acc = 0.f; cur = b;
        }
        acc += src[n * NF + c];
    }
    atomicAdd(&dstsum[cur * NF + c], acc);
}

// ---------------- center (g -= a*mean) + variance accumulation -------------
__global__ void gn_centervar_kernel(const float* __restrict__ a_row) {
    int c = threadIdx.x;
    int n0 = blockIdx.x * 128;
    int nend = min(n0 + 128, N_NODES);
    float a = a_row[c];
    float* gp = (float*)g_g4;
    const float* gs = (const float*)g_gsum4;
    float* vs = (float*)g_vsum4;
    int cur = g_batch[n0];
    float mean = gs[cur * NF + c] / g_cnt[cur];
    float vacc = 0.f;
    for (int n = n0; n < nend; n++) {
        int b = g_batch[n];
        if (b != cur) {
            atomicAdd(&vs[cur * NF + c], vacc);
            vacc = 0.f; cur = b;
            mean = gs[cur * NF + c] / g_cnt[cur];
        }
        float o = gp[n * NF + c] - a * mean;
        gp[n * NF + c] = o;
        vacc += o * o;
    }
    atomicAdd(&vs[cur * NF + c], vacc);
}

// ---------------- normalize + affine + relu + residual ---------------------
__global__ void gn_finalize_kernel(const float* __restrict__ w_row,
                                   const float* __restrict__ b_row, int residual) {
    int c = threadIdx.x;
    int n0 = blockIdx.x * 128;
    int nend = min(n0 + 128, N_NODES);
    float w = w_row[c], bb = b_row[c];
    const float* gp = (const float*)g_g4;
    const float* vs = (const float*)g_vsum4;
    float* hp = (float*)g_h4;
    int cur = -1;
    float inv = 0.f;
    for (int n = n0; n < nend; n++) {
        int b = g_batch[n];
        if (b != cur) {
            cur = b;
            inv = rsqrtf(vs[cur * NF + c] / g_cnt[cur] + EPS);
        }
        float v = fmaxf(fmaf(w * gp[n * NF + c], inv, bb), 0.f);
        hp[n * NF + c] = residual ? (v + hp[n * NF + c]) : v;
    }
}

// ---------------- head:  out[g] = dot(psum[g]/cnt[g], lin_w) + lin_b -------
__global__ void out_kernel(const float* __restrict__ linw,
                           const float* __restrict__ linb, float* __restrict__ out) {
    int wid = threadIdx.x >> 5;   // graph
    int lane = threadIdx.x & 31;
    const float* ps = (const float*)g_psum4;
    float v = 0.f;
    for (int c = lane; c < NF; c += 32) v += ps[wid * NF + c] * linw[c];
    #pragma unroll
    for (int off = 16; off > 0; off >>= 1)
        v += __shfl_down_sync(0xffffffffu, v, off);
    if (lane == 0) out[wid] = v / g_cnt[wid] + linb[0];
}

// ---------------- launcher --------------------------------------------------
extern "C" void kernel_launch(void* const* d_in, const int* in_sizes, int n_in,
                              void* d_out, int out_size) {
    const float* x    = (const float*)d_in[0];
    const int* ei_raw = (const int*)d_in[1];
    const int* b_raw  = (const int*)d_in[2];
    const float* W1   = (const float*)d_in[3];
    const float* b1   = (const float*)d_in[4];
    const float* W2   = (const float*)d_in[5];
    const float* b2   = (const float*)d_in[6];
    const float* gnw  = (const float*)d_in[7];
    const float* gnb  = (const float*)d_in[8];
    const float* gns  = (const float*)d_in[9];
    const float* linw = (const float*)d_in[10];
    const float* linb = (const float*)d_in[11];
    float* out = (float*)d_out;

    cudaFuncSetAttribute(mlp_kernel, cudaFuncAttributeMaxDynamicSharedMemorySize,
                         SMEM_MLP_BYTES);

    const int total_idx = 2 * N_EDGES + N_NODES;
    convert_kernel<<<(total_idx + 255) / 256, 256>>>(ei_raw, b_raw);
    cnt_kernel<<<1, 256>>>();

    for (int i = 0; i < NL; i++) {
        mlp_kernel<<<NBLK_NODES, 128, SMEM_MLP_BYTES>>>(
            x, i == 0, W1 + i * NF * NH, b1 + i * NH, W2 + i * NH * NF, b2 + i * NF);
        scatter_kernel<<<(N_EDGES + 7) / 8, 256>>>();
        seg_sum_kernel<<<NBLK_NODES, 128>>>(0);
        gn_centervar_kernel<<<NBLK_NODES, 128>>>(gns + i * NF);
        gn_finalize_kernel<<<NBLK_NODES, 128>>>(gnw + i * NF, gnb + i * NF, i > 0);
    }
    seg_sum_kernel<<<NBLK_NODES, 128>>>(1);
    out_kernel<<<1, NG * 32>>>(linw, linb, out);
}

// round 4
// speedup vs baseline: 2.0142x; 2.0142x over previous
#include <cuda_runtime.h>
#include <cuda_bf16.h>

#define N_NODES 20000
#define N_EDGES 320000
#define NF 128
#define NH 64
#define NG 16
#define NL 5
#define EPS 1e-5f
#define TILE 64
#define NBLK ((N_NODES + TILE - 1) / TILE)   // 313

// ---------------- scratch ---------------------------------------------------
__device__ float4 g_h4[N_NODES * NF / 4];     // running node features h
__device__ float4 g_m4[N_NODES * NF / 4];     // per-node MLP output m
__device__ float4 g_g4[N_NODES * NF / 4];     // aggregated features g
__device__ float  g_gsum[NG * NF];            // per-graph sum(g)
__device__ float  g_vsum[NG * NF];            // per-graph sum(g^2)
__device__ float  g_psum[NG * NF];            // pooled sums
__device__ float  g_A[NG * NF];               // norm scale  (w*inv)
__device__ float  g_B[NG * NF];               // norm shift  (b - A*a*mean)
__device__ float  g_cnt[NG];
__device__ int    g_src[N_EDGES];
__device__ int    g_dst[N_EDGES];
__device__ int    g_batch[N_NODES];
__device__ int    g_deg[N_NODES];
__device__ int    g_roff[N_NODES + 1];
__device__ int    g_cur[N_NODES];
__device__ int    g_eidx[N_EDGES];

// ---------------- index width detect + convert + zero scratch ---------------
__global__ void convert_kernel(const int* __restrict__ ei,
                               const int* __restrict__ braw) {
    __shared__ int s64;
    if (threadIdx.x == 0) {
        int all0 = 1;
        #pragma unroll 1
        for (int i = 1; i < 256; i += 2) all0 &= (ei[i] == 0);
        s64 = all0;
    }
    __syncthreads();
    int is64 = s64;
    int idx = blockIdx.x * blockDim.x + threadIdx.x;
    if (idx < N_EDGES) {
        g_src[idx] = is64 ? ei[2 * idx] : ei[idx];
    } else if (idx < 2 * N_EDGES) {
        int e = idx - N_EDGES;
        g_dst[e] = is64 ? ei[2 * N_EDGES + 2 * e] : ei[N_EDGES + e];
    } else if (idx < 2 * N_EDGES + N_NODES) {
        int n = idx - 2 * N_EDGES;
        g_batch[n] = is64 ? braw[2 * n] : braw[n];
    } else if (idx < 2 * N_EDGES + 2 * N_NODES) {
        g_deg[idx - 2 * N_EDGES - N_NODES] = 0;
    } else {
        int r = idx - 2 * N_EDGES - 2 * N_NODES;
        if (r < NG * NF) g_gsum[r] = 0.f;
        else if (r < 2 * NG * NF) g_vsum[r - NG * NF] = 0.f;
        else if (r < 3 * NG * NF) g_psum[r - 2 * NG * NF] = 0.f;
    }
}

// ---------------- CSR build --------------------------------------------------
__global__ void deg_kernel() {
    int e = blockIdx.x * blockDim.x + threadIdx.x;
    if (e < N_EDGES) atomicAdd(&g_deg[g_dst[e]], 1);
}

__global__ void scan_kernel() {   // 1 block, 1024 threads
    __shared__ int part[1024];
    int t = threadIdx.x;
    const int CH = (N_NODES + 1023) / 1024;   // 20
    int base = t * CH;
    int s = 0;
    for (int i = 0; i < CH; i++) {
        int idx = base + i;
        if (idx < N_NODES) s += g_deg[idx];
    }
    part[t] = s;
    __syncthreads();
    for (int off = 1; off < 1024; off <<= 1) {
        int v = (t >= off) ? part[t - off] : 0;
        __syncthreads();
        part[t] += v;
        __syncthreads();
    }
    int run = part[t] - s;     // exclusive
    for (int i = 0; i < CH; i++) {
        int idx = base + i;
        if (idx < N_NODES) {
            g_roff[idx] = run;
            g_cur[idx] = run;
            run += g_deg[idx];
        }
    }
    if (t == 1023) g_roff[N_NODES] = part[1023];
}

__global__ void fill_kernel() {
    int e = blockIdx.x * blockDim.x + threadIdx.x;
    if (e < N_EDGES) {
        int d = g_dst[e];
        int p = atomicAdd(&g_cur[d], 1);
        g_eidx[p] = g_src[e];
    }
}

// ---------------- per-graph counts via binary search (batch sorted) ---------
__global__ void cnt_kernel() {
    __shared__ int start[NG + 1];
    int t = threadIdx.x;
    if (t <= NG) {
        int lo = 0, hi = N_NODES;
        while (lo < hi) {
            int mid = (lo + hi) >> 1;
            if (g_batch[mid] < t) lo = mid + 1; else hi = mid;
        }
        start[t] = lo;
    }
    __syncthreads();
    if (t < NG) g_cnt[t] = fmaxf((float)(start[t + 1] - start[t]), 1.f);
}

// ---------------- fused MLP: m = relu(h@W1+b1)@W2+b2 ------------------------
// 2 threads per node (split-k gemm1 + butterfly, split-c gemm2).
#define SMEM_MLP_BYTES ((NF * NH + NH * NF + NH + NF) * 4)

__global__ void __launch_bounds__(128, 2)
mlp_kernel(const float* __restrict__ x, int first,
           const float* __restrict__ W1, const float* __restrict__ b1,
           const float* __restrict__ W2, const float* __restrict__ b2) {
    extern __shared__ float sm[];
    float* sW1 = sm;                   // [128][64]
    float* sW2 = sm + NF * NH;         // [64][128]
    float* sb1 = sW2 + NH * NF;
    float* sb2 = sb1 + NH;

    int tid = threadIdx.x;
    for (int i = tid; i < NF * NH; i += 128) { sW1[i] = W1[i]; sW2[i] = W2[i]; }
    if (tid < NH) sb1[tid] = b1[tid];
    sb2[tid] = b2[tid];
    __syncthreads();

    int local = tid >> 1, half = tid & 1;
    int n = blockIdx.x * TILE + local;
    bool active = (n < N_NODES);
    const float4* hin4 = first ? (const float4*)x : (const float4*)g_h4;

    float hid[NH];
    #pragma unroll
    for (int j = 0; j < NH; j++) hid[j] = 0.f;

    if (active) {
        const float4* hr = hin4 + n * (NF / 4) + half * (NF / 8);   // 16 float4
        #pragma unroll 4
        for (int i = 0; i < 16; i++) {
            float4 hv = hr[i];
            int k0 = half * 64 + i * 4;
            float hk[4] = {hv.x, hv.y, hv.z, hv.w};
            #pragma unroll
            for (int kk = 0; kk < 4; kk++) {
                const float4* wr = (const float4*)(sW1 + (k0 + kk) * NH);
                float hv1 = hk[kk];
                #pragma unroll
                for (int j4 = 0; j4 < NH / 4; j4++) {
                    float4 w = wr[j4];
                    hid[4 * j4 + 0] = fmaf(hv1, w.x, hid[4 * j4 + 0]);
                    hid[4 * j4 + 1] = fmaf(hv1, w.y, hid[4 * j4 + 1]);
                    hid[4 * j4 + 2] = fmaf(hv1, w.z, hid[4 * j4 + 2]);
                    hid[4 * j4 + 3] = fmaf(hv1, w.w, hid[4 * j4 + 3]);
                }
            }
        }
    }
    // combine the two k-halves, bias, relu (all threads participate in shfl)
    #pragma unroll
    for (int j = 0; j < NH; j++) {
        float v = hid[j] + __shfl_xor_sync(0xffffffffu, hid[j], 1);
        hid[j] = fmaxf(v + sb1[j], 0.f);
    }

    if (active) {
        #pragma unroll
        for (int cc = 0; cc < 2; cc++) {
            int cb = half * 64 + cc * 32;
            float4 acc[8];
            const float4* b2v = (const float4*)(sb2 + cb);
            #pragma unroll
            for (int q = 0; q < 8; q++) acc[q] = b2v[q];
            #pragma unroll 8
            for (int j = 0; j < NH; j++) {
                float hj = hid[j];
                const float4* wr = (const float4*)(sW2 + j * NF + cb);
                #pragma unroll
                for (int q = 0; q < 8; q++) {
                    float4 w = wr[q];
                    acc[q].x = fmaf(hj, w.x, acc[q].x);
                    acc[q].y = fmaf(hj, w.y, acc[q].y);
                    acc[q].z = fmaf(hj, w.z, acc[q].z);
                    acc[q].w = fmaf(hj, w.w, acc[q].w);
                }
            }
            float4* mo = g_m4 + n * (NF / 4) + cb / 4;
            #pragma unroll
            for (int q = 0; q < 8; q++) mo[q] = acc[q];
        }
    }
}

// ---------------- CSR gather: g[i] = m[i] + sum_{e:dst=i} m[src[e]] ---------
__global__ void gather_kernel() {
    int w = (blockIdx.x * blockDim.x + threadIdx.x) >> 5;
    int lane = threadIdx.x & 31;
    if (w >= N_NODES) return;
    float4 acc = g_m4[w * (NF / 4) + lane];          // self loop
    int r0 = g_roff[w], r1 = g_roff[w + 1];
    for (int base = r0; base < r1; base += 32) {
        int cnt = min(32, r1 - base);
        int s = (base + lane < r1) ? g_eidx[base + lane] : 0;
        for (int j = 0; j < cnt; j++) {
            int sj = __shfl_sync(0xffffffffu, s, j);
            float4 v = g_m4[sj * (NF / 4) + lane];
            acc.x += v.x; acc.y += v.y; acc.z += v.z; acc.w += v.w;
        }
    }
    g_g4[w * (NF / 4) + lane] = acc;
}

// ---------------- segmented sums (sorted batch) -----------------------------
// mode 0: g_g4 -> gsum (+ vsum of squares)   mode 1: g_h4 -> psum
// NOTE: source pointer is selected INSIDE the kernel — __device__ symbols
// must not be passed as arguments from host code.
__global__ void seg_kernel(int mode) {
    const float* src = mode ? (const float*)g_h4 : (const float*)g_g4;
    int c = threadIdx.x;
    int n0 = blockIdx.x * TILE;
    int nend = min(n0 + TILE, N_NODES);
    int cur = g_batch[n0];
    float acc = 0.f, acc2 = 0.f;
    for (int n = n0; n < nend; n++) {
        int b = g_batch[n];
        if (b != cur) {
            if (mode == 0) {
                atomicAdd(&g_gsum[cur * NF + c], acc);
                atomicAdd(&g_vsum[cur * NF + c], acc2);
            } else atomicAdd(&g_psum[cur * NF + c], acc);
            acc = 0.f; acc2 = 0.f; cur = b;
        }
        float v = src[n * NF + c];
        acc += v;
        if (mode == 0) acc2 += v * v;
    }
    if (mode == 0) {
        atomicAdd(&g_gsum[cur * NF + c], acc);
        atomicAdd(&g_vsum[cur * NF + c], acc2);
    } else atomicAdd(&g_psum[cur * NF + c], acc);
}

// ---------------- stats: per-(graph,feature) affine A,B; zero accumulators --
__global__ void stats_kernel(const float* __restrict__ w_row,
                             const float* __restrict__ b_row,
                             const float* __restrict__ a_row) {
    int g = blockIdx.x, c = threadIdx.x;
    int i = g * NF + c;
    float cg = g_cnt[g];
    float mean = g_gsum[i] / cg;
    float E2 = g_vsum[i] / cg;
    float a = a_row[c];
    float var = E2 - 2.f * a * mean * mean + a * a * mean * mean;
    float inv = rsqrtf(var + EPS);
    float A = w_row[c] * inv;
    g_A[i] = A;
    g_B[i] = b_row[c] - A * a * mean;
    g_gsum[i] = 0.f;
    g_vsum[i] = 0.f;
}

// ---------------- finalize: h = relu(A*g + B) (+ h) -------------------------
__global__ void finalize_kernel(int residual) {
    int c = threadIdx.x;
    int n0 = blockIdx.x * TILE;
    int nend = min(n0 + TILE, N_NODES);
    const float* gp = (const float*)g_g4;
    float* hp = (float*)g_h4;
    int cur = -1;
    float A = 0.f, B = 0.f;
    for (int n = n0; n < nend; n++) {
        int b = g_batch[n];
        if (b != cur) { cur = b; A = g_A[b * NF + c]; B = g_B[b * NF + c]; }
        float v = fmaxf(fmaf(A, gp[n * NF + c], B), 0.f);
        hp[n * NF + c] = residual ? (v + hp[n * NF + c]) : v;
    }
}

// ---------------- head ------------------------------------------------------
__global__ void out_kernel(const float* __restrict__ linw,
                           const float* __restrict__ linb, float* __restrict__ out) {
    int g = threadIdx.x >> 5;
    int lane = threadIdx.x & 31;
    float v = 0.f;
    for (int c = lane; c < NF; c += 32) v += g_psum[g * NF + c] * linw[c];
    #pragma unroll
    for (int off = 16; off > 0; off >>= 1)
        v += __shfl_down_sync(0xffffffffu, v, off);
    if (lane == 0) out[g] = v / g_cnt[g] + linb[0];
}

// ---------------- launcher --------------------------------------------------
extern "C" void kernel_launch(void* const* d_in, const int* in_sizes, int n_in,
                              void* d_out, int out_size) {
    const float* x    = (const float*)d_in[0];
    const int* ei_raw = (const int*)d_in[1];
    const int* b_raw  = (const int*)d_in[2];
    const float* W1   = (const float*)d_in[3];
    const float* b1   = (const float*)d_in[4];
    const float* W2   = (const float*)d_in[5];
    const float* b2   = (const float*)d_in[6];
    const float* gnw  = (const float*)d_in[7];
    const float* gnb  = (const float*)d_in[8];
    const float* gns  = (const float*)d_in[9];
    const float* linw = (const float*)d_in[10];
    const float* linb = (const float*)d_in[11];
    float* out = (float*)d_out;

    cudaFuncSetAttribute(mlp_kernel, cudaFuncAttributeMaxDynamicSharedMemorySize,
                         SMEM_MLP_BYTES);

    const int total_cv = 2 * N_EDGES + 2 * N_NODES + 3 * NG * NF;
    convert_kernel<<<(total_cv + 255) / 256, 256>>>(ei_raw, b_raw);
    deg_kernel<<<(N_EDGES + 255) / 256, 256>>>();
    scan_kernel<<<1, 1024>>>();
    fill_kernel<<<(N_EDGES + 255) / 256, 256>>>();
    cnt_kernel<<<1, 32>>>();

    for (int i = 0; i < NL; i++) {
        mlp_kernel<<<NBLK, 128, SMEM_MLP_BYTES>>>(
            x, i == 0, W1 + i * NF * NH, b1 + i * NH, W2 + i * NH * NF, b2 + i * NF);
        gather_kernel<<<(N_NODES * 32 + 255) / 256, 256>>>();
        seg_kernel<<<NBLK, 128>>>(0);
        stats_kernel<<<NG, 128>>>(gnw + i * NF, gnb + i * NF, gns + i * NF);
        finalize_kernel<<<NBLK, 128>>>(i > 0);
    }
    seg_kernel<<<NBLK, 128>>>(1);
    out_kernel<<<1, NG * 32>>>(linw, linb, out);
}

// round 5
// speedup vs baseline: 2.4587x; 1.2207x over previous
#include <cuda_runtime.h>

typedef unsigned long long u64;

#define N_NODES 20000
#define N_EDGES 320000
#define NF 128
#define NH 64
#define NG 16
#define NL 5
#define EPS 1e-5f
#define TILE 64
#define NBLK ((N_NODES + TILE - 1) / TILE)   // 313
#define GB_BLOCKS 296
#define GB_WARPS (GB_BLOCKS * 8)

// ---------------- scratch ---------------------------------------------------
__device__ float4 g_h4[N_NODES * NF / 4];
__device__ float4 g_m4[N_NODES * NF / 4];
__device__ float4 g_g4[N_NODES * NF / 4];
__device__ float  g_gsum[NG * NF];
__device__ float  g_vsum[NG * NF];
__device__ float  g_psum[NG * NF];
__device__ float  g_A[NG * NF];
__device__ float  g_B[NG * NF];
__device__ float  g_cnt[NG];
__device__ int    g_src[N_EDGES];
__device__ int    g_dst[N_EDGES];
__device__ int    g_batch[N_NODES];
__device__ int    g_deg[N_NODES];
__device__ int    g_roff[N_NODES + 1];
__device__ int    g_cur[N_NODES];
__device__ int    g_eidx[N_EDGES];

// ---------------- f32x2 + red helpers ---------------------------------------
__device__ __forceinline__ u64 pack2(float lo, float hi) {
    u64 r; asm("mov.b64 %0,{%1,%2};" : "=l"(r) : "f"(lo), "f"(hi)); return r;
}
__device__ __forceinline__ float2 unpack2(u64 v) {
    float2 f; asm("mov.b64 {%0,%1},%2;" : "=f"(f.x), "=f"(f.y) : "l"(v)); return f;
}
__device__ __forceinline__ void fma2(u64& d, u64 a, u64 b) {
    asm("fma.rn.f32x2 %0,%1,%2,%0;" : "+l"(d) : "l"(a), "l"(b));
}
__device__ __forceinline__ void red_v4(float* p, float4 v) {
    asm volatile("red.global.add.v4.f32 [%0],{%1,%2,%3,%4};"
                 :: "l"(p), "f"(v.x), "f"(v.y), "f"(v.z), "f"(v.w) : "memory");
}

// ---------------- convert: detect idx width, copy, zero scratch -------------
__global__ void convert_kernel(const int* __restrict__ ei,
                               const int* __restrict__ braw) {
    __shared__ int s64;
    if (threadIdx.x == 0) {
        int all0 = 1;
        #pragma unroll 1
        for (int i = 1; i < 256; i += 2) all0 &= (ei[i] == 0);
        s64 = all0;
    }
    __syncthreads();
    int is64 = s64;
    int idx = blockIdx.x * blockDim.x + threadIdx.x;
    if (idx < N_EDGES) {
        g_src[idx] = is64 ? ei[2 * idx] : ei[idx];
    } else if (idx < 2 * N_EDGES) {
        int e = idx - N_EDGES;
        g_dst[e] = is64 ? ei[2 * N_EDGES + 2 * e] : ei[N_EDGES + e];
    } else if (idx < 2 * N_EDGES + N_NODES) {
        int n = idx - 2 * N_EDGES;
        g_batch[n] = is64 ? braw[2 * n] : braw[n];
    } else if (idx < 2 * N_EDGES + 2 * N_NODES) {
        g_deg[idx - 2 * N_EDGES - N_NODES] = 0;
    } else {
        int r = idx - 2 * N_EDGES - 2 * N_NODES;
        if (r < NG * NF) g_gsum[r] = 0.f;
        else if (r < 2 * NG * NF) g_vsum[r - NG * NF] = 0.f;
        else if (r < 3 * NG * NF) g_psum[r - 2 * NG * NF] = 0.f;
    }
}

__global__ void deg_kernel() {
    int e = blockIdx.x * blockDim.x + threadIdx.x;
    if (e < N_EDGES) atomicAdd(&g_deg[g_dst[e]], 1);
}

// ---------------- scan (CSR offsets) + per-graph counts ---------------------
__global__ void scan_kernel() {   // 1 block, 1024 threads
    __shared__ int part[1024];
    __shared__ int start[NG + 1];
    int t = threadIdx.x;
    if (t <= NG) {   // binary search graph starts in sorted batch
        int lo = 0, hi = N_NODES;
        while (lo < hi) {
            int mid = (lo + hi) >> 1;
            if (g_batch[mid] < t) lo = mid + 1; else hi = mid;
        }
        start[t] = lo;
    }
    const int CH = (N_NODES + 1023) / 1024;   // 20
    int base = t * CH;
    int s = 0;
    for (int i = 0; i < CH; i++) {
        int idx = base + i;
        if (idx < N_NODES) s += g_deg[idx];
    }
    part[t] = s;
    __syncthreads();
    for (int off = 1; off < 1024; off <<= 1) {
        int v = (t >= off) ? part[t - off] : 0;
        __syncthreads();
        part[t] += v;
        __syncthreads();
    }
    int run = part[t] - s;     // exclusive
    for (int i = 0; i < CH; i++) {
        int idx = base + i;
        if (idx < N_NODES) {
            g_roff[idx] = run;
            g_cur[idx] = run;
            run += g_deg[idx];
        }
    }
    if (t == 1023) g_roff[N_NODES] = part[1023];
    if (t < NG) g_cnt[t] = fmaxf((float)(start[t + 1] - start[t]), 1.f);
}

__global__ void fill_kernel() {
    int e = blockIdx.x * blockDim.x + threadIdx.x;
    if (e < N_EDGES) {
        int d = g_dst[e];
        int p = atomicAdd(&g_cur[d], 1);
        g_eidx[p] = g_src[e];
    }
}

// ---------------- fused finalize(prev layer) + MLP --------------------------
// mode 0: h := x (layer 0).  mode 1: h := relu(A*g+B) (finalize layer0).
// mode 2: h := relu(A*g+B) + h_old (residual).
// 128 threads, 2 threads per node (k-split gemm1, c-split gemm2), f32x2 FMAs.
#define SMEM_MLP_BYTES ((NF * NH + NH * NF + NH + NF) * 4)

__global__ void __launch_bounds__(128)
mlp_kernel(const float* __restrict__ x, int mode,
           const float* __restrict__ W1, const float* __restrict__ b1,
           const float* __restrict__ W2, const float* __restrict__ b2) {
    extern __shared__ float sm[];
    float* sW1 = sm;                   // [128][64]
    float* sW2 = sm + NF * NH;         // [64][128]
    float* sb1 = sW2 + NH * NF;
    float* sb2 = sb1 + NH;

    int tid = threadIdx.x;
    for (int i = tid; i < NF * NH; i += 128) { sW1[i] = W1[i]; sW2[i] = W2[i]; }
    if (tid < NH) sb1[tid] = b1[tid];
    sb2[tid] = b2[tid];
    __syncthreads();

    int local = tid >> 1, half = tid & 1, c0 = half * NH;
    int n = blockIdx.x * TILE + local;
    bool act = (n < N_NODES);
    int nsafe = act ? n : 0;

    const float4* grow = (const float4*)((const float*)g_g4 + nsafe * NF + c0);
    const float4* hrow = (const float4*)((const float*)g_h4 + nsafe * NF + c0);
    const float4* xrow = (const float4*)(x + nsafe * NF + c0);
    int b = act ? g_batch[n] : 0;
    const float4* Arow = (const float4*)(g_A + b * NF + c0);
    const float4* Brow = (const float4*)(g_B + b * NF + c0);
    float4* hout = (float4*)((float*)g_h4 + nsafe * NF + c0);

    u64 hid2[32];
    #pragma unroll
    for (int q = 0; q < 32; q++) hid2[q] = 0ull;

    // --- phase 1 (finalize / input read) fused with gemm1 -------------------
    #pragma unroll 4
    for (int i = 0; i < 16; i++) {
        float4 h;
        if (mode == 0) {
            h = act ? xrow[i] : make_float4(0.f, 0.f, 0.f, 0.f);
        } else {
            float4 gv = act ? grow[i] : make_float4(0.f, 0.f, 0.f, 0.f);
            float4 Av = Arow[i], Bv = Brow[i];
            h.x = fmaxf(fmaf(Av.x, gv.x, Bv.x), 0.f);
            h.y = fmaxf(fmaf(Av.y, gv.y, Bv.y), 0.f);
            h.z = fmaxf(fmaf(Av.z, gv.z, Bv.z), 0.f);
            h.w = fmaxf(fmaf(Av.w, gv.w, Bv.w), 0.f);
            if (mode == 2 && act) {
                float4 ho = hrow[i];
                h.x += ho.x; h.y += ho.y; h.z += ho.z; h.w += ho.w;
            }
            if (act) hout[i] = h;
        }
        float hk[4] = {h.x, h.y, h.z, h.w};
        #pragma unroll
        for (int kk = 0; kk < 4; kk++) {
            u64 pk = pack2(hk[kk], hk[kk]);
            const ulonglong2* wr = (const ulonglong2*)(sW1 + (c0 + 4 * i + kk) * NH);
            #pragma unroll
            for (int q8 = 0; q8 < 16; q8++) {
                ulonglong2 w = wr[q8];
                fma2(hid2[2 * q8], pk, w.x);
                fma2(hid2[2 * q8 + 1], pk, w.y);
            }
        }
    }

    // --- combine k-halves + relu, fused with gemm2 --------------------------
    u64 acc2[32];
    const ulonglong2* bb = (const ulonglong2*)(sb2 + c0);
    #pragma unroll
    for (int q8 = 0; q8 < 16; q8++) {
        ulonglong2 v = bb[q8];
        acc2[2 * q8] = v.x; acc2[2 * q8 + 1] = v.y;
    }
    #pragma unroll
    for (int q = 0; q < 32; q++) {
        float2 f = unpack2(hid2[q]);
        f.x += __shfl_xor_sync(0xffffffffu, f.x, 1);
        f.y += __shfl_xor_sync(0xffffffffu, f.y, 1);
        float h0 = fmaxf(f.x + sb1[2 * q], 0.f);
        float h1 = fmaxf(f.y + sb1[2 * q + 1], 0.f);
        u64 p0 = pack2(h0, h0), p1 = pack2(h1, h1);
        const ulonglong2* w0 = (const ulonglong2*)(sW2 + (2 * q) * NF + c0);
        const ulonglong2* w1 = (const ulonglong2*)(sW2 + (2 * q + 1) * NF + c0);
        #pragma unroll
        for (int q8 = 0; q8 < 16; q8++) {
            ulonglong2 a = w0[q8], c = w1[q8];
            fma2(acc2[2 * q8], p0, a.x);
            fma2(acc2[2 * q8 + 1], p0, a.y);
            fma2(acc2[2 * q8], p1, c.x);
            fma2(acc2[2 * q8 + 1], p1, c.y);
        }
    }
    if (act) {
        ulonglong2* mo = (ulonglong2*)((float*)g_m4 + n * NF + c0);
        #pragma unroll
        for (int q8 = 0; q8 < 16; q8++) {
            ulonglong2 v; v.x = acc2[2 * q8]; v.y = acc2[2 * q8 + 1];
            mo[q8] = v;
        }
    }
}

// ---------------- gather (CSR) + segmented gsum/vsum fused -------------------
// Warp per contiguous node chunk; run-length seg accumulation in registers.
__global__ void __launch_bounds__(256)
gather_kernel() {
    int w = (blockIdx.x * blockDim.x + threadIdx.x) >> 5;
    int lane = threadIdx.x & 31;
    const int CH = (N_NODES + GB_WARPS - 1) / GB_WARPS;  // 9
    int n0 = w * CH;
    if (n0 >= N_NODES) return;
    int n1 = min(n0 + CH, N_NODES);

    int cur = g_batch[n0];
    float4 seg = make_float4(0.f, 0.f, 0.f, 0.f);
    float4 seg2 = make_float4(0.f, 0.f, 0.f, 0.f);

    for (int n = n0; n < n1; n++) {
        int bb = g_batch[n];
        if (bb != cur) {
            red_v4(&g_gsum[cur * NF + lane * 4], seg);
            red_v4(&g_vsum[cur * NF + lane * 4], seg2);
            seg = make_float4(0.f, 0.f, 0.f, 0.f);
            seg2 = make_float4(0.f, 0.f, 0.f, 0.f);
            cur = bb;
        }
        float4 a0 = g_m4[n * 32 + lane];            // self loop
        float4 a1 = make_float4(0.f, 0.f, 0.f, 0.f), a2 = a1, a3 = a1;
        int r0 = g_roff[n], r1 = g_roff[n + 1];
        for (int base = r0; base < r1; base += 32) {
            int cnt = min(32, r1 - base);
            int s = (base + lane < r1) ? g_eidx[base + lane] : 0;
            int j = 0;
            for (; j + 4 <= cnt; j += 4) {
                int s0 = __shfl_sync(0xffffffffu, s, j);
                int s1 = __shfl_sync(0xffffffffu, s, j + 1);
                int s2 = __shfl_sync(0xffffffffu, s, j + 2);
                int s3 = __shfl_sync(0xffffffffu, s, j + 3);
                float4 v0 = g_m4[s0 * 32 + lane];
                float4 v1 = g_m4[s1 * 32 + lane];
                float4 v2 = g_m4[s2 * 32 + lane];
                float4 v3 = g_m4[s3 * 32 + lane];
                a0.x += v0.x; a0.y += v0.y; a0.z += v0.z; a0.w += v0.w;
                a1.x += v1.x; a1.y += v1.y; a1.z += v1.z; a1.w += v1.w;
                a2.x += v2.x; a2.y += v2.y; a2.z += v2.z; a2.w += v2.w;
                a3.x += v3.x; a3.y += v3.y; a3.z += v3.z; a3.w += v3.w;
            }
            for (; j < cnt; j++) {
                int sj = __shfl_sync(0xffffffffu, s, j);
                float4 v = g_m4[sj * 32 + lane];
                a0.x += v.x; a0.y += v.y; a0.z += v.z; a0.w += v.w;
            }
        }
        a0.x += a1.x + a2.x + a3.x;
        a0.y += a1.y + a2.y + a3.y;
        a0.z += a1.z + a2.z + a3.z;
        a0.w += a1.w + a2.w + a3.w;
        g_g4[n * 32 + lane] = a0;
        seg.x += a0.x; seg.y += a0.y; seg.z += a0.z; seg.w += a0.w;
        seg2.x += a0.x * a0.x; seg2.y += a0.y * a0.y;
        seg2.z += a0.z * a0.z; seg2.w += a0.w * a0.w;
    }
    red_v4(&g_gsum[cur * NF + lane * 4], seg);
    red_v4(&g_vsum[cur * NF + lane * 4], seg2);
}

// ---------------- stats: per-(graph,feature) affine A,B; re-zero accums -----
__global__ void stats_kernel(const float* __restrict__ w_row,
                             const float* __restrict__ b_row,
                             const float* __restrict__ a_row) {
    int g = blockIdx.x, c = threadIdx.x;
    int i = g * NF + c;
    float cg = g_cnt[g];
    float mean = g_gsum[i] / cg;
    float E2 = g_vsum[i] / cg;
    float a = a_row[c];
    float var = E2 - 2.f * a * mean * mean + a * a * mean * mean;
    float inv = rsqrtf(var + EPS);
    float A = w_row[c] * inv;
    g_A[i] = A;
    g_B[i] = b_row[c] - A * a * mean;
    g_gsum[i] = 0.f;
    g_vsum[i] = 0.f;
}

// ---------------- final: finalize(last layer) + mean-pool accumulation ------
__global__ void __launch_bounds__(128)
final_kernel() {
    int tid = threadIdx.x, local = tid >> 1, half = tid & 1, c0 = half * NH;
    int lane = tid & 31;
    int n = blockIdx.x * TILE + local;
    bool act = (n < N_NODES);
    int nsafe = act ? n : 0;
    int b = act ? g_batch[n] : 0;

    const float4* grow = (const float4*)((const float*)g_g4 + nsafe * NF + c0);
    const float4* hrow = (const float4*)((const float*)g_h4 + nsafe * NF + c0);
    const float4* Arow = (const float4*)(g_A + b * NF + c0);
    const float4* Brow = (const float4*)(g_B + b * NF + c0);

    float4 hv[16];
    #pragma unroll
    for (int i = 0; i < 16; i++) {
        if (act) {
            float4 gv = grow[i], Av = Arow[i], Bv = Brow[i], ho = hrow[i];
            hv[i].x = fmaxf(fmaf(Av.x, gv.x, Bv.x), 0.f) + ho.x;
            hv[i].y = fmaxf(fmaf(Av.y, gv.y, Bv.y), 0.f) + ho.y;
            hv[i].z = fmaxf(fmaf(Av.z, gv.z, Bv.z), 0.f) + ho.z;
            hv[i].w = fmaxf(fmaf(Av.w, gv.w, Bv.w), 0.f) + ho.w;
        } else {
            hv[i] = make_float4(0.f, 0.f, 0.f, 0.f);
        }
    }
    int b0 = __shfl_sync(0xffffffffu, b, 0);
    bool same = __all_sync(0xffffffffu, (!act) || b == b0);
    if (same) {
        #pragma unroll
        for (int off = 2; off < 32; off <<= 1) {
            #pragma unroll
            for (int i = 0; i < 16; i++) {
                hv[i].x += __shfl_xor_sync(0xffffffffu, hv[i].x, off);
                hv[i].y += __shfl_xor_sync(0xffffffffu, hv[i].y, off);
                hv[i].z += __shfl_xor_sync(0xffffffffu, hv[i].z, off);
                hv[i].w += __shfl_xor_sync(0xffffffffu, hv[i].w, off);
            }
        }
        if (lane < 2) {
            #pragma unroll
            for (int i = 0; i < 16; i++)
                red_v4(&g_psum[b0 * NF + c0 + 4 * i], hv[i]);
        }
    } else if (act) {
        #pragma unroll
        for (int i = 0; i < 16; i++)
            red_v4(&g_psum[b * NF + c0 + 4 * i], hv[i]);
    }
}

// ---------------- head ------------------------------------------------------
__global__ void out_kernel(const float* __restrict__ linw,
                           const float* __restrict__ linb, float* __restrict__ out) {
    int g = threadIdx.x >> 5;
    int lane = threadIdx.x & 31;
    float v = 0.f;
    for (int c = lane; c < NF; c += 32) v += g_psum[g * NF + c] * linw[c];
    #pragma unroll
    for (int off = 16; off > 0; off >>= 1)
        v += __shfl_down_sync(0xffffffffu, v, off);
    if (lane == 0) out[g] = v / g_cnt[g] + linb[0];
}

// ---------------- launcher --------------------------------------------------
extern "C" void kernel_launch(void* const* d_in, const int* in_sizes, int n_in,
                              void* d_out, int out_size) {
    const float* x    = (const float*)d_in[0];
    const int* ei_raw = (const int*)d_in[1];
    const int* b_raw  = (const int*)d_in[2];
    const float* W1   = (const float*)d_in[3];
    const float* b1   = (const float*)d_in[4];
    const float* W2   = (const float*)d_in[5];
    const float* b2   = (const float*)d_in[6];
    const float* gnw  = (const float*)d_in[7];
    const float* gnb  = (const float*)d_in[8];
    const float* gns  = (const float*)d_in[9];
    const float* linw = (const float*)d_in[10];
    const float* linb = (const float*)d_in[11];
    float* out = (float*)d_out;

    cudaFuncSetAttribute(mlp_kernel, cudaFuncAttributeMaxDynamicSharedMemorySize,
                         SMEM_MLP_BYTES);

    const int total_cv = 2 * N_EDGES + 2 * N_NODES + 3 * NG * NF;
    convert_kernel<<<(total_cv + 255) / 256, 256>>>(ei_raw, b_raw);
    deg_kernel<<<(N_EDGES + 255) / 256, 256>>>();
    scan_kernel<<<1, 1024>>>();
    fill_kernel<<<(N_EDGES + 255) / 256, 256>>>();

    for (int i = 0; i < NL; i++) {
        int mode = (i == 0) ? 0 : ((i == 1) ? 1 : 2);
        mlp_kernel<<<NBLK, 128, SMEM_MLP_BYTES>>>(
            x, mode, W1 + i * NF * NH, b1 + i * NH, W2 + i * NH * NF, b2 + i * NF);
        gather_kernel<<<GB_BLOCKS, 256>>>();
        stats_kernel<<<NG, 128>>>(gnw + i * NF, gnb + i * NF, gns + i * NF);
    }
    final_kernel<<<NBLK, 128>>>();
    out_kernel<<<1, NG * 32>>>(linw, linb, out);
}